// round 13
// baseline (speedup 1.0000x reference)
#include <cuda_runtime.h>

#define Bn 64
#define Tn 512
#define Ln 48
#define HALF 256
#define STARTL 46
#define ENDL 47
#define PFD 4
#define NCTA 128
#define LOG2E_F 1.4426950408889634f
#define LN2_F   0.6931471805599453f

__device__ __forceinline__ float ex2f_(float x){float r;asm("ex2.approx.f32 %0,%1;":"=f"(r):"f"(x));return r;}
__device__ __forceinline__ float lg2f_(float x){float r;asm("lg2.approx.f32 %0,%1;":"=f"(r):"f"(x));return r;}
__device__ __forceinline__ unsigned long long pack2_(float a,float b){
    unsigned long long d;asm("mov.b64 %0,{%1,%2};":"=l"(d):"f"(a),"f"(b));return d;}
__device__ __forceinline__ void unpack2_(unsigned long long d,float&a,float&b){
    asm("mov.b64 {%0,%1},%2;":"=f"(a),"=f"(b):"l"(d));}
__device__ __forceinline__ void fma2_(unsigned long long&d,unsigned long long a,unsigned long long b){
    asm("fma.rn.f32x2 %0,%1,%2,%0;":"+l"(d):"l"(a),"l"(b));}
__device__ __forceinline__ unsigned long long mul2_(unsigned long long a,unsigned long long b){
    unsigned long long d;asm("mul.rn.f32x2 %0,%1,%2;":"=l"(d):"l"(a),"l"(b));return d;}
__device__ __forceinline__ unsigned long long add2_(unsigned long long a,unsigned long long b){
    unsigned long long d;asm("add.rn.f32x2 %0,%1,%2;":"=l"(d):"l"(a),"l"(b));return d;}

// cross-CTA scratch
__device__ float g_scr[2][Bn][64];   // [dir][batch][48 used]
__device__ int   c_scr[2][Bn];       // exponent accumulators
__device__ float e_scr[Bn];          // gold-path energy per batch
__device__ int   done_ctr = 0;       // last-block-done counter (reset by last block)

// matvec: v[12] pairs (from HS) dot shared w[24] -> GPOUT   (input-dim f32x2 SIMD)
#define MATVEC(GPOUT) \
    unsigned long long a0 = mul2_(v[0].x, w[0]);                               \
    unsigned long long a1 = mul2_(v[0].y, w[1]);                               \
    unsigned long long a2 = mul2_(v[1].x, w[2]);                               \
    unsigned long long a3 = mul2_(v[1].y, w[3]);                               \
    _Pragma("unroll") for (int p = 4; p < 24; p += 4){                         \
        fma2_(a0, v[(p>>1)    ].x, w[p  ]);                                    \
        fma2_(a1, v[(p>>1)    ].y, w[p+1]);                                    \
        fma2_(a2, v[(p>>1) + 1].x, w[p+2]);                                    \
        fma2_(a3, v[(p>>1) + 1].y, w[p+3]);                                    \
    }                                                                          \
    unsigned long long s01_ = add2_(a0, a1);                                   \
    unsigned long long s23_ = add2_(a2, a3);                                   \
    unsigned long long sal_ = add2_(s01_, s23_);                               \
    float lo_, hi_; unpack2_(sal_, lo_, hi_);                                  \
    float GPOUT = lo_ + hi_;

// prologue: load state, exp prefetched emission, refill prefetch, derive
// power-of-2 renorm scale from h[0]'s (clamped) exponent. ue clamp >= 87
// bounds scale <= 2^40 so scale*e can't overflow on near-zero states
// (first backward step). C2 logs the SAME clamped exponent -> exact.
#define STEP_PRE(HS, CUR, PFV, PFIDX, SP, C2)                                  \
    const ulonglong2* hp_ = (const ulonglong2*)((HS) + (CUR));                 \
    ulonglong2 v[12];                                                          \
    _Pragma("unroll") for (int j = 0; j < 12; j++) v[j] = hp_[j];              \
    float e_ = ex2f_((PFV) * LOG2E_F);                                         \
    PFV = (SP)[(PFIDX) * Ln];                                                  \
    float h0_, hxx_; unpack2_(v[0].x, h0_, hxx_);                              \
    unsigned ue_ = __float_as_uint(h0_) >> 23;                                 \
    ue_ = ue_ < 87u ? 87u : ue_;                                               \
    C2 += (int)ue_;                                                            \
    float scale_ = __uint_as_float((254u - ue_) << 23);                        \
    float se_ = scale_ * e_;

// ---- per-chain bodies (NO barrier inside; caller barriers once per pair) ----
#define BODY_FAST(HS, CUR, NXT, PFV, PFIDX, SP, GP, LS, C2) do {               \
    STEP_PRE(HS, CUR, PFV, PFIDX, SP, C2)                                      \
    MATVEC(gp_)                                                                \
    GP = gp_; LS = scale_;                                                     \
    if (tid < Ln) (HS)[(NXT) + tid] = gp_ * se_;                               \
} while(0)

#define BODY_FGEN(HS, CUR, NXT, PFV, PFIDX, SP, GP, C2, MV) do {               \
    STEP_PRE(HS, CUR, PFV, PFIDX, SP, C2)                                      \
    MATVEC(gp_)                                                                \
    float gsel_ = (MV) ? gp_ : GP;                                             \
    GP = gsel_ * scale_;                                                       \
    if (tid < Ln) (HS)[(NXT) + tid] = gsel_ * se_;                             \
} while(0)

#define BODY_BGEN(HS, CUR, NXT, PFV, PFIDX, SP, GP, C2, MV) do {               \
    STEP_PRE(HS, CUR, PFV, PFIDX, SP, C2)                                      \
    MATVEC(gp_)                                                                \
    float cand_ = gp_ * e_;                                                    \
    float bsel_ = (MV) ? cand_ : GP;                                           \
    GP = bsel_ * scale_;                                                       \
    if (tid < Ln) (HS)[(NXT) + tid] = GP;                                      \
} while(0)

__global__ __launch_bounds__(64,1)
void crf_fused(const float* __restrict__ scores,
               const int*   __restrict__ gold_i,   // int32 view (may really be int64)
               const int*   __restrict__ mask,
               const float* __restrict__ trans,
               float*       __restrict__ out)
{
    __shared__ float h_shA[2*Ln];
    __shared__ float h_shB[2*Ln];
    __shared__ int   mA_sh[Tn];
    __shared__ int   mB_sh[Tn];
    __shared__ float ps[64];
    __shared__ int   flag_sh[1];

    const int tid = threadIdx.x;
    const int bx  = blockIdx.x;

    const int yy = (tid < Ln) ? tid : 0;

    if (bx < 64) {
        // ================= chain CTA: two batches, one direction =================
        const int dir = bx >> 5;          // 0=fwd, 1=bwd
        const int p   = bx & 31;
        const int bA  = p, bB = p + 32;
        const float* spA = scores + (size_t)bA * Tn * Ln + yy;
        const float* spB = scores + (size_t)bB * Tn * Ln + yy;

        // stage both mask rows + all-ones detect (one barrier)
        int myok = 1;
        {
            const int4* mAs = (const int4*)(mask + bA * Tn);
            const int4* mBs = (const int4*)(mask + bB * Tn);
            #pragma unroll
            for (int i = tid; i < Tn/4; i += 64){
                int4 a4 = mAs[i], b4 = mBs[i];
                ((int4*)mA_sh)[i] = a4;
                ((int4*)mB_sh)[i] = b4;
                myok &= (a4.x==1)&(a4.y==1)&(a4.z==1)&(a4.w==1)
                      & (b4.x==1)&(b4.y==1)&(b4.z==1)&(b4.w==1);
            }
        }
        const int fastpath = __syncthreads_and(myok);

        unsigned long long w[24];
        int   cA = 0, cB = 0;
        float gA, gB, lsA = 1.0f, lsB = 1.0f;

        if (dir == 0) {
            // w = column yy of W = exp(trans)
            #pragma unroll
            for (int j = 0; j < 24; j++){
                float wa = ex2f_(trans[(2*j  )*Ln + yy] * LOG2E_F);
                float wb = ex2f_(trans[(2*j+1)*Ln + yy] * LOG2E_F);
                w[j] = pack2_(wa, wb);
            }
            float pA0=spA[1*Ln], pA1=spA[2*Ln], pA2=spA[3*Ln], pA3=spA[4*Ln];
            float pB0=spB[1*Ln], pB1=spB[2*Ln], pB2=spB[3*Ln], pB3=spB[4*Ln];
            float ts = trans[STARTL*Ln + yy];
            gA = ex2f_(ts * LOG2E_F);  gB = gA;
            if (tid < Ln){
                h_shA[tid] = ex2f_((ts + spA[0]) * LOG2E_F);
                h_shB[tid] = ex2f_((ts + spB[0]) * LOG2E_F);
            }
            __syncthreads();

            if (fastpath){
                for (int t = 0; t < HALF; t += 4){
                    BODY_FAST(h_shA,0 ,Ln,pA0,t+1+PFD,spA,gA,lsA,cA);
                    BODY_FAST(h_shB,0 ,Ln,pB0,t+1+PFD,spB,gB,lsB,cB);
                    __syncthreads();
                    BODY_FAST(h_shA,Ln,0 ,pA1,t+2+PFD,spA,gA,lsA,cA);
                    BODY_FAST(h_shB,Ln,0 ,pB1,t+2+PFD,spB,gB,lsB,cB);
                    __syncthreads();
                    BODY_FAST(h_shA,0 ,Ln,pA2,t+3+PFD,spA,gA,lsA,cA);
                    BODY_FAST(h_shB,0 ,Ln,pB2,t+3+PFD,spB,gB,lsB,cB);
                    __syncthreads();
                    BODY_FAST(h_shA,Ln,0 ,pA3,t+4+PFD,spA,gA,lsA,cA);
                    BODY_FAST(h_shB,Ln,0 ,pB3,t+4+PFD,spB,gB,lsB,cB);
                    __syncthreads();
                }
                gA *= lsA;  gB *= lsB;          // fold final renorm
            } else {
                for (int t = 0; t < HALF; t += 4){
                    BODY_FGEN(h_shA,0 ,Ln,pA0,t+1+PFD,spA,gA,cA,mA_sh[t  ]);
                    BODY_FGEN(h_shB,0 ,Ln,pB0,t+1+PFD,spB,gB,cB,mB_sh[t  ]);
                    __syncthreads();
                    BODY_FGEN(h_shA,Ln,0 ,pA1,t+2+PFD,spA,gA,cA,mA_sh[t+1]);
                    BODY_FGEN(h_shB,Ln,0 ,pB1,t+2+PFD,spB,gB,cB,mB_sh[t+1]);
                    __syncthreads();
                    BODY_FGEN(h_shA,0 ,Ln,pA2,t+3+PFD,spA,gA,cA,mA_sh[t+2]);
                    BODY_FGEN(h_shB,0 ,Ln,pB2,t+3+PFD,spB,gB,cB,mB_sh[t+2]);
                    __syncthreads();
                    BODY_FGEN(h_shA,Ln,0 ,pA3,t+4+PFD,spA,gA,cA,mA_sh[t+3]);
                    BODY_FGEN(h_shB,Ln,0 ,pB3,t+4+PFD,spB,gB,cB,mB_sh[t+3]);
                    __syncthreads();
                }
            }
            if (tid < Ln){ g_scr[0][bA][tid] = gA; g_scr[0][bB][tid] = gB; }
            if (tid == 0){ c_scr[0][bA] = cA; c_scr[0][bB] = cB; }
        } else {
            // w = row yy of W
            #pragma unroll
            for (int j = 0; j < 24; j++){
                float wa = ex2f_(trans[yy*Ln + 2*j    ] * LOG2E_F);
                float wb = ex2f_(trans[yy*Ln + 2*j + 1] * LOG2E_F);
                w[j] = pack2_(wa, wb);
            }
            float pA0=spA[511*Ln], pA1=spA[510*Ln], pA2=spA[509*Ln], pA3=spA[508*Ln];
            float pB0=spB[511*Ln], pB1=spB[510*Ln], pB2=spB[509*Ln], pB3=spB[508*Ln];
            // beta_512 = delta_END * 2^-64 (bias compensated by +64 in combine)
            gA = (yy == ENDL) ? 0x1p-64f : 0.0f;  gB = gA;
            if (tid < Ln){ h_shA[tid] = gA; h_shB[tid] = gB; }
            __syncthreads();

            if (fastpath){
                for (int t = Tn-1; t >= HALF+3; t -= 4){
                    BODY_FAST(h_shA,0 ,Ln,pA0,t  -PFD,spA,gA,lsA,cA);
                    BODY_FAST(h_shB,0 ,Ln,pB0,t  -PFD,spB,gB,lsB,cB);
                    __syncthreads();
                    BODY_FAST(h_shA,Ln,0 ,pA1,t-1-PFD,spA,gA,lsA,cA);
                    BODY_FAST(h_shB,Ln,0 ,pB1,t-1-PFD,spB,gB,lsB,cB);
                    __syncthreads();
                    BODY_FAST(h_shA,0 ,Ln,pA2,t-2-PFD,spA,gA,lsA,cA);
                    BODY_FAST(h_shB,0 ,Ln,pB2,t-2-PFD,spB,gB,lsB,cB);
                    __syncthreads();
                    BODY_FAST(h_shA,Ln,0 ,pA3,t-3-PFD,spA,gA,lsA,cA);
                    BODY_FAST(h_shB,Ln,0 ,pB3,t-3-PFD,spB,gB,lsB,cB);
                    __syncthreads();
                }
                // the WRITTEN state each step is the true carried beta; after
                // 256 (even) steps it sits in buffer 0
                if (tid < Ln){ gA = h_shA[tid]; gB = h_shB[tid]; }
            } else {
                for (int t = Tn-1; t >= HALF+3; t -= 4){
                    BODY_BGEN(h_shA,0 ,Ln,pA0,t  -PFD,spA,gA,cA,mA_sh[t  ]);
                    BODY_BGEN(h_shB,0 ,Ln,pB0,t  -PFD,spB,gB,cB,mB_sh[t  ]);
                    __syncthreads();
                    BODY_BGEN(h_shA,Ln,0 ,pA1,t-1-PFD,spA,gA,cA,mA_sh[t-1]);
                    BODY_BGEN(h_shB,Ln,0 ,pB1,t-1-PFD,spB,gB,cB,mB_sh[t-1]);
                    __syncthreads();
                    BODY_BGEN(h_shA,0 ,Ln,pA2,t-2-PFD,spA,gA,cA,mA_sh[t-2]);
                    BODY_BGEN(h_shB,0 ,Ln,pB2,t-2-PFD,spB,gB,cB,mB_sh[t-2]);
                    __syncthreads();
                    BODY_BGEN(h_shA,Ln,0 ,pA3,t-3-PFD,spA,gA,cA,mA_sh[t-3]);
                    BODY_BGEN(h_shB,Ln,0 ,pB3,t-3-PFD,spB,gB,cB,mB_sh[t-3]);
                    __syncthreads();
                }
            }
            if (tid < Ln){ g_scr[1][bA][tid] = gA; g_scr[1][bB][tid] = gB; }
            if (tid == 0){ c_scr[1][bA] = cA; c_scr[1][bB] = cB; }
        }
    } else {
        // ========== gold-path energy: sum_t mask*(scores[b,t,0]+trans[0,gold]) ==========
        const int b = bx - 64;
        float* t0_sh = (float*)mA_sh;           // reuse smem
        if (tid < Ln) t0_sh[tid] = trans[tid];  // trans row 0
        if (tid == 0){                          // gold dtype detect (int64 hi-words zero)
            int f = 1;
            #pragma unroll
            for (int j = 0; j < 32; j++) f &= (gold_i[2*j+1] == 0);
            flag_sh[0] = f;
        }
        __syncthreads();
        const int is64 = flag_sh[0];
        const float* sb0 = scores + (size_t)b * Tn * Ln;
        const int*   mb  = mask + b * Tn;
        float pe = 0.0f;
        #pragma unroll 4
        for (int tt = tid; tt < Tn; tt += 64){
            int idx = b*Tn + tt;
            int g   = is64 ? gold_i[2*idx] : gold_i[idx];
            pe += (float)mb[tt] * (sb0[tt*Ln] + t0_sh[g]);
        }
        ps[tid] = pe;
        __syncthreads();
        if (tid == 0){
            float tot = 0.0f;
            #pragma unroll
            for (int i = 0; i < 64; i++) tot += ps[i];
            e_scr[b] = tot;
        }
    }

    // ---- last-CTA combine ----
    __syncthreads();
    if (tid == 0){
        __threadfence();
        int prev = atomicAdd(&done_ctr, 1);
        flag_sh[0] = (prev == NCTA - 1);
    }
    __syncthreads();
    if (!flag_sh[0]) return;
    __threadfence();

    // each thread handles one batch
    {
        const int bb = tid;
        float Z = 0.0f;
        const float* gf = g_scr[0][bb];
        const float* gb = g_scr[1][bb];
        #pragma unroll
        for (int i = 0; i < Ln; i++) Z += gf[i] * gb[i];
        int bias = c_scr[0][bb] + c_scr[1][bb] - 127*Tn + 64;
        float fsend = ((float)bias + lg2f_(Z)) * LN2_F;
        ps[tid] = fsend - e_scr[bb];
    }
    __syncthreads();
    if (tid == 0){
        float acc = 0.0f;
        #pragma unroll
        for (int i = 0; i < 64; i++) acc += ps[i];
        float tStart = trans[STARTL];   // trans[0][START]
        out[0] = (acc - (float)Bn * tStart) * (1.0f / (float)Bn);
        __threadfence();
        done_ctr = 0;                   // reset for next graph replay
    }
}

extern "C" void kernel_launch(void* const* d_in, const int* in_sizes, int n_in,
                              void* d_out, int out_size)
{
    const float* scores = (const float*)d_in[0];
    const int*   gold   = (const int*)  d_in[1];
    const int*   mask   = (const int*)  d_in[2];
    const float* trans  = (const float*)d_in[3];
    float* out = (float*)d_out;

    crf_fused<<<NCTA, 64>>>(scores, gold, mask, trans, out);
}